// round 14
// baseline (speedup 1.0000x reference)
#include <cuda_runtime.h>
#include <math.h>

#define DD 32
#define NWARP 4
#define THREADS (NWARP * 32)
#define CUTOFF_F 6.0f
#define PI_F 3.14159265358979323846f
#define FULLMASK 0xffffffffu

// rows: 12 floats (3 x float4) per (batch,atom): [pv0..pv8, fx, fy, fz]
// stats tail (at float offset bn*12): [Etot(b)..., pad to 32, virial(9b)...]
// Zero at module load; the in-kernel pack phase re-zeroes everything it
// reads, so scratch is zero at every kernel_launch entry (deterministic).
__device__ float4 g_scratch[32768 * 3 + 64];
// monotonic device-wide barrier counter (never reset; generation = t/G)
__device__ unsigned long long g_ctr = 0ULL;

// ---------------------------------------------------------------------------
__device__ __forceinline__ float ftanh(float x) {
    float y;
    asm("tanh.approx.f32 %0, %1;" : "=f"(y) : "f"(x));
    return y;
}
__device__ __forceinline__ float warp_sum(float v) {
#pragma unroll
    for (int o = 16; o; o >>= 1) v += __shfl_xor_sync(FULLMASK, v, o);
    return v;
}
// three independent warp reductions, interleaved level-by-level so the SHFL
// chains overlap (latency ~5 levels instead of 15)
__device__ __forceinline__ void warp_sum3(float& x, float& y, float& z) {
#pragma unroll
    for (int o = 16; o; o >>= 1) {
        float tx = __shfl_xor_sync(FULLMASK, x, o);
        float ty = __shfl_xor_sync(FULLMASK, y, o);
        float tz = __shfl_xor_sync(FULLMASK, z, o);
        x += tx; y += ty; z += tz;
    }
}
__device__ __forceinline__ void red_add_v4(float* p, float a, float b, float c, float d) {
    asm volatile("red.global.add.v4.f32 [%0], {%1,%2,%3,%4};"
                 :: "l"(p), "f"(a), "f"(b), "f"(c), "f"(d) : "memory");
}
__device__ __forceinline__ void flush_stats(float (&vir)[9], float& etot, int cur_bi,
                                            float* __restrict__ st, int lane) {
    // 9 independent chains; interleave in triples
    warp_sum3(vir[0], vir[1], vir[2]);
    warp_sum3(vir[3], vir[4], vir[5]);
    warp_sum3(vir[6], vir[7], vir[8]);
    if (lane == 0) {
#pragma unroll
        for (int q = 0; q < 9; q++) atomicAdd(&st[32 + cur_bi * 9 + q], vir[q]);
        atomicAdd(&st[cur_bi], etot);
    }
#pragma unroll
    for (int q = 0; q < 9; q++) vir[q] = 0.0f;
    etot = 0.0f;
}

// ---------------------------------------------------------------------------
// Persistent warp-per-atom kernel + device-wide barrier + in-kernel pack.
// Lane owns neighbors (lane, lane+32). h cached in smem for channels 0..15
// via 128-bit STS/LDS (20-float row stride, conflict-free), recomputed in
// backward for 16..31. Next atom's inputs software-prefetched; bias via
// scalar broadcast LDS.
// ---------------------------------------------------------------------------
template<bool FULL>
__global__ __launch_bounds__(THREADS, 6) void field_kernel(
    const int* __restrict__ element_map,
    const int* __restrict__ neighbor_indices,
    const int* __restrict__ neighbor_types,
    const float4* __restrict__ neighbor_vectors,
    const float* __restrict__ type_embed,
    const float* __restrict__ elem_bias,
    const float* __restrict__ W1, const float* __restrict__ b1,
    const float* __restrict__ W2, const float* __restrict__ b2,
    const float* __restrict__ W3, const float* __restrict__ b3,
    float* __restrict__ out,
    int b, int n, int m, int ntypes)
{
    __shared__ __align__(16) float4 w1c4[DD];     // (W1[0][k],W1[1][k],W1[2][k],W1[3][k])
    __shared__ __align__(16) float biaskt[DD][4]; // [k][tt]: b1[k]+type_embed[tt][k]
    __shared__ float W2s[DD][DD + 1];
    __shared__ float b2s[DD], W3s[DD];
    __shared__ __align__(16) float gmb[NWARP][DD];
    __shared__ __align__(16) float dh2b[NWARP][DD];
    __shared__ __align__(16) float dhb[NWARP][DD];
    // h for channels 0..15: [warp][neighbor j][16 channels + 4 pad]
    __shared__ __align__(16) float hc[NWARP][64][20];

    const int tid  = threadIdx.x;
    const int lane = tid & 31;
    const int wid  = tid >> 5;

    for (int idx = tid; idx < DD * DD; idx += THREADS)
        W2s[idx >> 5][idx & 31] = W2[idx];
    if (tid < DD) {
        w1c4[tid] = make_float4(W1[tid], W1[DD + tid], W1[2 * DD + tid], W1[3 * DD + tid]);
        float bb = b1[tid];
        biaskt[tid][0] = bb + type_embed[tid];
        biaskt[tid][1] = (ntypes > 1) ? bb + type_embed[DD + tid] : 0.0f;
        biaskt[tid][2] = (ntypes > 2) ? bb + type_embed[2 * DD + tid] : 0.0f;
        biaskt[tid][3] = 0.0f;
        b2s[tid] = b2[tid];
        W3s[tid] = W3[tid];
    }
    __syncthreads();

    const float b2k = b2s[lane], w3k = W3s[lane];
    const float b3v = __ldg(b3);
    const float invC = PI_F / CUTOFF_F;
    const float c1 = -0.5f * invC;
    const float inv_m = 1.0f / (float)m;

    const long total = (long)b * n;
    float* outEi = out + b;
    float* st = (float*)g_scratch + total * 12;

    const int  G = gridDim.x;
    const long nwarps = (long)G * NWARP;
    const long apw = (total + nwarps - 1) / nwarps;
    const long gw = (long)blockIdx.x * NWARP + wid;
    long a0 = gw * apw;
    long a1 = a0 + apw; if (a1 > total) a1 = total;

    const bool v0b = FULL || (lane < m);
    const bool v1b = FULL || (lane + 32 < m);

    if (a0 < total) {
        float vir[9];
#pragma unroll
        for (int q = 0; q < 9; q++) vir[q] = 0.0f;
        float etot = 0.0f;

        const float4* gm4  = (const float4*)gmb[wid];
        const float4* dh24 = (const float4*)dh2b[wid];
        const float4* dh4  = (const float4*)dhb[wid];

        // incremental (bi, ai) bookkeeping (no per-atom division)
        int bi = (int)(a0 / n);
        int ai = (int)(a0 - (long)bi * n);
        int cur_bi = bi;

        // ---- prefetch state for atom a0 ----
        float4 pnv0 = make_float4(0,0,0,0), pnv1 = make_float4(0,0,0,0);
        int pni0 = 0x7fffffff, pni1 = 0x7fffffff, ptt0 = 3, ptt1 = 3;
        {
            const long base = a0 * m + lane;
            if (v0b) {
                pnv0 = __ldg(&neighbor_vectors[base]);
                pni0 = __ldg(&neighbor_indices[base]);
                ptt0 = __ldg(&neighbor_types[base]);
            }
            if (v1b) {
                pnv1 = __ldg(&neighbor_vectors[base + 32]);
                pni1 = __ldg(&neighbor_indices[base + 32]);
                ptt1 = __ldg(&neighbor_types[base + 32]);
            }
        }

        for (long atom = a0; atom < a1; ++atom) {
            if (bi != cur_bi) {
                flush_stats(vir, etot, cur_bi, st, lane);
                cur_bi = bi;
            }

            // ------------ P0: consume prefetched inputs --------------------
            const float rx0 = pnv0.y, ry0 = pnv0.z, rz0 = pnv0.w;
            const float rx1 = pnv1.y, ry1 = pnv1.z, rz1 = pnv1.w;
            const int tt0 = ptt0, tt1 = ptt1, ni0 = pni0, ni1 = pni1;
            float s0 = 0.f, d0 = 0.f, ivd0 = 0.f, e0 = 0.f;
            float s1 = 0.f, d1 = 0.f, ivd1 = 0.f, e1 = 0.f;
            if (v0b) {
                float r2 = rx0 * rx0 + ry0 * ry0 + rz0 * rz0;
                ivd0 = rsqrtf(r2);
                d0 = r2 * ivd0;
                float fc = 0.5f * (__cosf(fminf(d0, CUTOFF_F) * invC) + 1.0f);
                e0 = __expf(-d0);
                s0 = e0 * fc;
            }
            if (v1b) {
                float r2 = rx1 * rx1 + ry1 * ry1 + rz1 * rz1;
                ivd1 = rsqrtf(r2);
                d1 = r2 * ivd1;
                float fc = 0.5f * (__cosf(fminf(d1, CUTOFF_F) * invC) + 1.0f);
                e1 = __expf(-d1);
                s1 = e1 * fc;
            }

            // ---- prefetch next atom's inputs (hidden behind P1..P3) -------
            if (atom + 1 < a1) {
                const long base = (atom + 1) * m + lane;
                if (v0b) {
                    pnv0 = __ldg(&neighbor_vectors[base]);
                    pni0 = __ldg(&neighbor_indices[base]);
                    ptt0 = __ldg(&neighbor_types[base]);
                }
                if (v1b) {
                    pnv1 = __ldg(&neighbor_vectors[base + 32]);
                    pni1 = __ldg(&neighbor_indices[base + 32]);
                    ptt1 = __ldg(&neighbor_types[base + 32]);
                }
            }

            // ------------ P1: forward; g[lane] via 4-channel reduces -------
            float g = 0.0f;
#pragma unroll 4
            for (int q = 0; q < 8; q++) {
                float v[4];
                float hv0[4], hv1[4];
#pragma unroll
                for (int r = 0; r < 4; r++) {
                    const int k = 4 * q + r;
                    const float4 w = w1c4[k];
                    float bias0 = biaskt[k][tt0];      // broadcast LDS
                    float bias1 = biaskt[k][tt1];
                    float t0 = fmaf(rz0, w.w, fmaf(ry0, w.z, fmaf(rx0, w.y, w.x)));
                    float t1 = fmaf(rz1, w.w, fmaf(ry1, w.z, fmaf(rx1, w.y, w.x)));
                    float h0 = ftanh(fmaf(s0, t0, bias0));
                    float h1 = ftanh(fmaf(s1, t1, bias1));
                    hv0[r] = h0; hv1[r] = h1;
                    if (!FULL) { h0 = v0b ? h0 : 0.0f; h1 = v1b ? h1 : 0.0f; }
                    v[r] = h0 + h1;
                }
                if (q < 4) {                           // cache channels 0..15 (128-bit)
                    *(float4*)&hc[wid][lane][4 * q] =
                        make_float4(hv0[0], hv0[1], hv0[2], hv0[3]);
                    *(float4*)&hc[wid][lane + 32][4 * q] =
                        make_float4(hv1[0], hv1[1], hv1[2], hv1[3]);
                }
                // 4-channel butterfly transpose-reduce
                {
                    const bool bb0 = lane & 1, bb1 = lane & 2;
                    float send0 = bb0 ? v[0] : v[1], keep0 = bb0 ? v[1] : v[0];
                    float a0r = keep0 + __shfl_xor_sync(FULLMASK, send0, 1);
                    float send1 = bb0 ? v[2] : v[3], keep1 = bb0 ? v[3] : v[2];
                    float a1r = keep1 + __shfl_xor_sync(FULLMASK, send1, 1);
                    float send2 = bb1 ? a0r : a1r, keep2 = bb1 ? a1r : a0r;
                    float t = keep2 + __shfl_xor_sync(FULLMASK, send2, 2);
                    t += __shfl_xor_sync(FULLMASK, t, 4);
                    t += __shfl_xor_sync(FULLMASK, t, 8);
                    t += __shfl_xor_sync(FULLMASK, t, 16);
                    if ((lane >> 2) == q) g = t;       // lane l ends with g[l]
                }
            }

            // ------------ P2: head (lane = channel) ------------------------
            gmb[wid][lane] = g * inv_m;
            __syncwarp();
            float c0a = b2k, c1a = 0.f, c2a = 0.f, c3a = 0.f;
#pragma unroll
            for (int q = 0; q < 8; q++) {
                float4 gv = gm4[q];
                c0a = fmaf(gv.x, W2s[4 * q + 0][lane], c0a);
                c1a = fmaf(gv.y, W2s[4 * q + 1][lane], c1a);
                c2a = fmaf(gv.z, W2s[4 * q + 2][lane], c2a);
                c3a = fmaf(gv.w, W2s[4 * q + 3][lane], c3a);
            }
            float h2 = ftanh((c0a + c1a) + (c2a + c3a));
            float esum = warp_sum(h2 * w3k);
            if (lane == 0) {
                int em = __ldg(&element_map[atom]);
                float Ei = esum + b3v + __ldg(&elem_bias[em]);
                outEi[atom] = Ei;
                etot += Ei;
            }
            dh2b[wid][lane] = (1.0f - h2 * h2) * w3k;
            __syncwarp();
            float dg0 = 0.f, dg1 = 0.f, dg2 = 0.f, dg3 = 0.f;
#pragma unroll
            for (int q = 0; q < 8; q++) {
                float4 dv = dh24[q];
                dg0 = fmaf(W2s[lane][4 * q + 0], dv.x, dg0);
                dg1 = fmaf(W2s[lane][4 * q + 1], dv.y, dg1);
                dg2 = fmaf(W2s[lane][4 * q + 2], dv.z, dg2);
                dg3 = fmaf(W2s[lane][4 * q + 3], dv.w, dg3);
            }
            dhb[wid][lane] = ((dg0 + dg1) + (dg2 + dg3)) * inv_m;
            __syncwarp();

            // ------------ P3: backward (lane = neighbor pair) --------------
            float f00 = 0.f, f01 = 0.f, f02 = 0.f, f03 = 0.f;
            float f10 = 0.f, f11 = 0.f, f12 = 0.f, f13 = 0.f;
#pragma unroll 2
            for (int q = 0; q < 4; q++) {          // cached channels (128-bit LDS)
                float4 dv = dh4[q];
                float4 h04 = *(const float4*)&hc[wid][lane][4 * q];
                float4 h14 = *(const float4*)&hc[wid][lane + 32][4 * q];
#pragma unroll
                for (int r = 0; r < 4; r++) {
                    const int k = 4 * q + r;
                    const float dhk = (r == 0) ? dv.x : (r == 1) ? dv.y : (r == 2) ? dv.z : dv.w;
                    const float h0 = (r == 0) ? h04.x : (r == 1) ? h04.y : (r == 2) ? h04.z : h04.w;
                    const float h1 = (r == 0) ? h14.x : (r == 1) ? h14.y : (r == 2) ? h14.z : h14.w;
                    const float4 w = w1c4[k];
                    float dp0 = dhk * fmaf(-h0, h0, 1.0f);
                    float dp1 = dhk * fmaf(-h1, h1, 1.0f);
                    f00 = fmaf(w.x, dp0, f00); f01 = fmaf(w.y, dp0, f01);
                    f02 = fmaf(w.z, dp0, f02); f03 = fmaf(w.w, dp0, f03);
                    f10 = fmaf(w.x, dp1, f10); f11 = fmaf(w.y, dp1, f11);
                    f12 = fmaf(w.z, dp1, f12); f13 = fmaf(w.w, dp1, f13);
                }
            }
#pragma unroll 2
            for (int q = 4; q < 8; q++) {          // recomputed channels
                float4 dv = dh4[q];
#pragma unroll
                for (int r = 0; r < 4; r++) {
                    const int k = 4 * q + r;
                    const float dhk = (r == 0) ? dv.x : (r == 1) ? dv.y : (r == 2) ? dv.z : dv.w;
                    const float4 w = w1c4[k];
                    float bias0 = biaskt[k][tt0];
                    float bias1 = biaskt[k][tt1];
                    float t0 = fmaf(rz0, w.w, fmaf(ry0, w.z, fmaf(rx0, w.y, w.x)));
                    float t1 = fmaf(rz1, w.w, fmaf(ry1, w.z, fmaf(rx1, w.y, w.x)));
                    float h0 = ftanh(fmaf(s0, t0, bias0));
                    float h1 = ftanh(fmaf(s1, t1, bias1));
                    float dp0 = dhk * fmaf(-h0, h0, 1.0f);
                    float dp1 = dhk * fmaf(-h1, h1, 1.0f);
                    f00 = fmaf(w.x, dp0, f00); f01 = fmaf(w.y, dp0, f01);
                    f02 = fmaf(w.z, dp0, f02); f03 = fmaf(w.w, dp0, f03);
                    f10 = fmaf(w.x, dp1, f10); f11 = fmaf(w.y, dp1, f11);
                    f12 = fmaf(w.z, dp1, f12); f13 = fmaf(w.w, dp1, f13);
                }
            }

            // ------------ epilogue per neighbor -----------------------------
            float cgx = 0.f, cgy = 0.f, cgz = 0.f;
#pragma unroll
            for (int nb = 0; nb < 2; nb++) {
                const bool valid = nb ? v1b : v0b;
                if (!valid) continue;
                const float rx = nb ? rx1 : rx0, ry = nb ? ry1 : ry0, rz = nb ? rz1 : rz0;
                const float s = nb ? s1 : s0, d = nb ? d1 : d0;
                const float ivd = nb ? ivd1 : ivd0, e = nb ? e1 : e0;
                const float fa = nb ? f10 : f00, fb = nb ? f11 : f01;
                const float fcq = nb ? f12 : f02, fd = nb ? f13 : f03;
                const int ni = nb ? ni1 : ni0;

                float fcp = (d < CUTOFF_F) ? (c1 * __sinf(d * invC)) : 0.0f;
                float ds = fa + rx * fb + ry * fcq + rz * fd;
                float dd = ds * fmaf(e, fcp, -s);  // e*(fcp - fc) = e*fcp - s
                float t2 = dd * ivd;
                float gx = fmaf(t2, rx, s * fb);
                float gy = fmaf(t2, ry, s * fcq);
                float gz = fmaf(t2, rz, s * fd);

                float pv0 = rx * gx, pv1 = rx * gy, pv2 = rx * gz;
                float pv3 = ry * gx, pv4 = ry * gy, pv5 = ry * gz;
                float pv6 = rz * gx, pv7 = rz * gy, pv8 = rz * gz;
                vir[0] += pv0; vir[1] += pv1; vir[2] += pv2;
                vir[3] += pv3; vir[4] += pv4; vir[5] += pv5;
                vir[6] += pv6; vir[7] += pv7; vir[8] += pv8;
                cgx += gx; cgy += gy; cgz += gz;

                if (ni < n) {
                    float* p = (float*)(g_scratch + ((long)bi * n + ni) * 3);
                    red_add_v4(p,     pv0, pv1, pv2, pv3);
                    red_add_v4(p + 4, pv4, pv5, pv6, pv7);
                    red_add_v4(p + 8, pv8, -gx, -gy, -gz);
                }
            }
            warp_sum3(cgx, cgy, cgz);
            if (lane == 0) {
                float* p = (float*)(g_scratch + ((long)bi * n + ai) * 3);
                red_add_v4(p + 8, 0.0f, cgx, cgy, cgz);
            }

            // incremental (bi, ai) advance
            if (++ai == n) { ai = 0; ++bi; }
        }
        flush_stats(vir, etot, cur_bi, st, lane);
    }

    // ================= device-wide barrier (ticket, monotonic) =============
    __syncthreads();
    if (tid == 0) {
        __threadfence();
        unsigned long long t = atomicAdd(&g_ctr, 1ULL);
        unsigned long long target = (t / (unsigned long long)G + 1ULL) * (unsigned long long)G;
        volatile unsigned long long* vc = (volatile unsigned long long*)&g_ctr;
        while (*vc < target) __nanosleep(128);
        __threadfence();
    }
    __syncthreads();

    // ================= pack phase (scratch -> out, then zero) ==============
    {
        const float4 z = make_float4(0.f, 0.f, 0.f, 0.f);
        const long stride = (long)G * THREADS;
        for (long i = (long)blockIdx.x * THREADS + tid; i < total; i += stride) {
            float4* r4 = &g_scratch[i * 3];
            float4 v0 = r4[0], v1 = r4[1], v2 = r4[2];
            r4[0] = z; r4[1] = z; r4[2] = z;
            float* outF  = out + b + total + i * 3;
            float* outAV = out + 10L * b + 4L * total + i * 9;
            outAV[0] = v0.x; outAV[1] = v0.y; outAV[2] = v0.z;
            outAV[3] = v0.w; outAV[4] = v1.x; outAV[5] = v1.y;
            outAV[6] = v1.z; outAV[7] = v1.w; outAV[8] = v2.x;
            outF[0] = v2.y; outF[1] = v2.z; outF[2] = v2.w;
        }
        if (blockIdx.x == 0) {
            for (int q = tid; q < b; q += THREADS) {
                out[q] = st[q]; st[q] = 0.0f;                          // Etot
            }
            for (int q = tid; q < 9 * b; q += THREADS) {
                out[b + 4L * total + q] = st[32 + q]; st[32 + q] = 0.0f; // virial
            }
        }
    }
}

// ---------------------------------------------------------------------------
extern "C" void kernel_launch(void* const* d_in, const int* in_sizes, int n_in,
                              void* d_out, int out_size) {
    const int*    element_map      = (const int*)d_in[0];
    const int*    neighbor_indices = (const int*)d_in[2];
    const int*    neighbor_types   = (const int*)d_in[3];
    const float4* neighbor_vectors = (const float4*)d_in[4];
    const float*  type_embed = (const float*)d_in[6];
    const float*  elem_bias  = (const float*)d_in[7];
    const float*  W1 = (const float*)d_in[8];
    const float*  b1 = (const float*)d_in[9];
    const float*  W2 = (const float*)d_in[10];
    const float*  b2 = (const float*)d_in[11];
    const float*  W3 = (const float*)d_in[12];
    const float*  b3 = (const float*)d_in[13];
    float* out = (float*)d_out;

    const int bn  = in_sizes[0];
    const int bnm = in_sizes[2];
    const int m   = bnm / bn;
    const int ntypes = in_sizes[7];
    int b = (int)(((long)out_size - 13L * bn) / 10L);
    if (b < 1) b = 1;
    const int n = bn / b;

    // persistent grid sized to exactly-resident occupancy (deadlock-free)
    int dev = 0;
    cudaGetDevice(&dev);
    int nsm = 0;
    cudaDeviceGetAttribute(&nsm, cudaDevAttrMultiProcessorCount, dev);
    if (nsm < 1) nsm = 148;
    int nb = 0;
    if (m == 64) {
        cudaOccupancyMaxActiveBlocksPerMultiprocessor(&nb, field_kernel<true>, THREADS, 0);
    } else {
        cudaOccupancyMaxActiveBlocksPerMultiprocessor(&nb, field_kernel<false>, THREADS, 0);
    }
    if (nb < 1) nb = 1;
    long grid = (long)nb * nsm;
    long maxBlocks = ((long)bn + NWARP - 1) / NWARP;
    if (grid > maxBlocks) grid = maxBlocks;
    if (grid < 1) grid = 1;

    if (m == 64) {
        field_kernel<true><<<(int)grid, THREADS>>>(element_map, neighbor_indices, neighbor_types,
                                                   neighbor_vectors, type_embed, elem_bias,
                                                   W1, b1, W2, b2, W3, b3, out, b, n, m, ntypes);
    } else {
        field_kernel<false><<<(int)grid, THREADS>>>(element_map, neighbor_indices, neighbor_types,
                                                    neighbor_vectors, type_embed, elem_bias,
                                                    W1, b1, W2, b2, W3, b3, out, b, n, m, ntypes);
    }
}

// round 15
// speedup vs baseline: 1.0807x; 1.0807x over previous
#include <cuda_runtime.h>
#include <math.h>

#define DD 32
#define NWARP 4
#define THREADS (NWARP * 32)
#define CUTOFF_F 6.0f
#define PI_F 3.14159265358979323846f
#define FULLMASK 0xffffffffu

// rows: 12 floats (3 x float4) per (batch,atom): [pv0..pv8, fx, fy, fz]
// stats tail (at float offset bn*12): [Etot(b)..., pad to 32, virial(9b)...]
// Zero at module load; the in-kernel pack phase re-zeroes everything it
// reads, so scratch is zero at every kernel_launch entry (deterministic).
__device__ float4 g_scratch[32768 * 3 + 64];
// monotonic device-wide barrier counter (never reset; generation = t/G)
__device__ unsigned long long g_ctr = 0ULL;

// ---------------------------------------------------------------------------
__device__ __forceinline__ float ftanh(float x) {
    float y;
    asm("tanh.approx.f32 %0, %1;" : "=f"(y) : "f"(x));
    return y;
}
__device__ __forceinline__ float warp_sum(float v) {
#pragma unroll
    for (int o = 16; o; o >>= 1) v += __shfl_xor_sync(FULLMASK, v, o);
    return v;
}
// three independent warp reductions, interleaved level-by-level so the SHFL
// chains overlap (latency ~5 levels instead of 15)
__device__ __forceinline__ void warp_sum3(float& x, float& y, float& z) {
#pragma unroll
    for (int o = 16; o; o >>= 1) {
        float tx = __shfl_xor_sync(FULLMASK, x, o);
        float ty = __shfl_xor_sync(FULLMASK, y, o);
        float tz = __shfl_xor_sync(FULLMASK, z, o);
        x += tx; y += ty; z += tz;
    }
}
__device__ __forceinline__ void red_add_v4(float* p, float a, float b, float c, float d) {
    asm volatile("red.global.add.v4.f32 [%0], {%1,%2,%3,%4};"
                 :: "l"(p), "f"(a), "f"(b), "f"(c), "f"(d) : "memory");
}
__device__ __forceinline__ void flush_stats(float (&vir)[9], float& etot, int cur_bi,
                                            float* __restrict__ st, int lane) {
    warp_sum3(vir[0], vir[1], vir[2]);
    warp_sum3(vir[3], vir[4], vir[5]);
    warp_sum3(vir[6], vir[7], vir[8]);
    if (lane == 0) {
#pragma unroll
        for (int q = 0; q < 9; q++) atomicAdd(&st[32 + cur_bi * 9 + q], vir[q]);
        atomicAdd(&st[cur_bi], etot);
    }
#pragma unroll
    for (int q = 0; q < 9; q++) vir[q] = 0.0f;
    etot = 0.0f;
}

// ---------------------------------------------------------------------------
// Persistent warp-per-atom kernel + device-wide barrier + in-kernel pack.
// Lane owns neighbors (lane, lane+32). h cached in smem for channels 0..15
// via 128-bit STS/LDS (20-float row stride, conflict-free), recomputed in
// backward for 16..31. Next atom's inputs software-prefetched; bias via
// scalar broadcast LDS. NO min-blocks cap: kernel wants ~96 regs (caps spill).
// ---------------------------------------------------------------------------
template<bool FULL>
__global__ __launch_bounds__(THREADS) void field_kernel(
    const int* __restrict__ element_map,
    const int* __restrict__ neighbor_indices,
    const int* __restrict__ neighbor_types,
    const float4* __restrict__ neighbor_vectors,
    const float* __restrict__ type_embed,
    const float* __restrict__ elem_bias,
    const float* __restrict__ W1, const float* __restrict__ b1,
    const float* __restrict__ W2, const float* __restrict__ b2,
    const float* __restrict__ W3, const float* __restrict__ b3,
    float* __restrict__ out,
    int b, int n, int m, int ntypes)
{
    __shared__ __align__(16) float4 w1c4[DD];     // (W1[0][k],W1[1][k],W1[2][k],W1[3][k])
    __shared__ __align__(16) float biaskt[DD][4]; // [k][tt]: b1[k]+type_embed[tt][k]
    __shared__ float W2s[DD][DD + 1];
    __shared__ float b2s[DD], W3s[DD];
    __shared__ __align__(16) float gmb[NWARP][DD];
    __shared__ __align__(16) float dh2b[NWARP][DD];
    __shared__ __align__(16) float dhb[NWARP][DD];
    // h for channels 0..15: [warp][neighbor j][16 channels + 4 pad]
    __shared__ __align__(16) float hc[NWARP][64][20];

    const int tid  = threadIdx.x;
    const int lane = tid & 31;
    const int wid  = tid >> 5;

    for (int idx = tid; idx < DD * DD; idx += THREADS)
        W2s[idx >> 5][idx & 31] = W2[idx];
    if (tid < DD) {
        w1c4[tid] = make_float4(W1[tid], W1[DD + tid], W1[2 * DD + tid], W1[3 * DD + tid]);
        float bb = b1[tid];
        biaskt[tid][0] = bb + type_embed[tid];
        biaskt[tid][1] = (ntypes > 1) ? bb + type_embed[DD + tid] : 0.0f;
        biaskt[tid][2] = (ntypes > 2) ? bb + type_embed[2 * DD + tid] : 0.0f;
        biaskt[tid][3] = 0.0f;
        b2s[tid] = b2[tid];
        W3s[tid] = W3[tid];
    }
    __syncthreads();

    const float b2k = b2s[lane], w3k = W3s[lane];
    const float b3v = __ldg(b3);
    const float invC = PI_F / CUTOFF_F;
    const float c1 = -0.5f * invC;
    const float inv_m = 1.0f / (float)m;

    const long total = (long)b * n;
    float* outEi = out + b;
    float* st = (float*)g_scratch + total * 12;

    const int  G = gridDim.x;
    const long nwarps = (long)G * NWARP;
    const long apw = (total + nwarps - 1) / nwarps;
    const long gw = (long)blockIdx.x * NWARP + wid;
    long a0 = gw * apw;
    long a1 = a0 + apw; if (a1 > total) a1 = total;

    const bool v0b = FULL || (lane < m);
    const bool v1b = FULL || (lane + 32 < m);

    if (a0 < total) {
        float vir[9];
#pragma unroll
        for (int q = 0; q < 9; q++) vir[q] = 0.0f;
        float etot = 0.0f;

        const float4* gm4  = (const float4*)gmb[wid];
        const float4* dh24 = (const float4*)dh2b[wid];
        const float4* dh4  = (const float4*)dhb[wid];

        // incremental (bi, ai) bookkeeping (no per-atom division)
        int bi = (int)(a0 / n);
        int ai = (int)(a0 - (long)bi * n);
        int cur_bi = bi;

        // ---- prefetch state for atom a0 ----
        float4 pnv0 = make_float4(0,0,0,0), pnv1 = make_float4(0,0,0,0);
        int pni0 = 0x7fffffff, pni1 = 0x7fffffff, ptt0 = 3, ptt1 = 3;
        {
            const long base = a0 * m + lane;
            if (v0b) {
                pnv0 = __ldg(&neighbor_vectors[base]);
                pni0 = __ldg(&neighbor_indices[base]);
                ptt0 = __ldg(&neighbor_types[base]);
            }
            if (v1b) {
                pnv1 = __ldg(&neighbor_vectors[base + 32]);
                pni1 = __ldg(&neighbor_indices[base + 32]);
                ptt1 = __ldg(&neighbor_types[base + 32]);
            }
        }

        for (long atom = a0; atom < a1; ++atom) {
            if (bi != cur_bi) {
                flush_stats(vir, etot, cur_bi, st, lane);
                cur_bi = bi;
            }

            // ------------ P0: consume prefetched inputs --------------------
            const float rx0 = pnv0.y, ry0 = pnv0.z, rz0 = pnv0.w;
            const float rx1 = pnv1.y, ry1 = pnv1.z, rz1 = pnv1.w;
            const int tt0 = ptt0, tt1 = ptt1, ni0 = pni0, ni1 = pni1;
            float s0 = 0.f, d0 = 0.f, ivd0 = 0.f, e0 = 0.f;
            float s1 = 0.f, d1 = 0.f, ivd1 = 0.f, e1 = 0.f;
            if (v0b) {
                float r2 = rx0 * rx0 + ry0 * ry0 + rz0 * rz0;
                ivd0 = rsqrtf(r2);
                d0 = r2 * ivd0;
                float fc = 0.5f * (__cosf(fminf(d0, CUTOFF_F) * invC) + 1.0f);
                e0 = __expf(-d0);
                s0 = e0 * fc;
            }
            if (v1b) {
                float r2 = rx1 * rx1 + ry1 * ry1 + rz1 * rz1;
                ivd1 = rsqrtf(r2);
                d1 = r2 * ivd1;
                float fc = 0.5f * (__cosf(fminf(d1, CUTOFF_F) * invC) + 1.0f);
                e1 = __expf(-d1);
                s1 = e1 * fc;
            }

            // ---- prefetch next atom's inputs (hidden behind P1..P3) -------
            if (atom + 1 < a1) {
                const long base = (atom + 1) * m + lane;
                if (v0b) {
                    pnv0 = __ldg(&neighbor_vectors[base]);
                    pni0 = __ldg(&neighbor_indices[base]);
                    ptt0 = __ldg(&neighbor_types[base]);
                }
                if (v1b) {
                    pnv1 = __ldg(&neighbor_vectors[base + 32]);
                    pni1 = __ldg(&neighbor_indices[base + 32]);
                    ptt1 = __ldg(&neighbor_types[base + 32]);
                }
            }

            // ------------ P1: forward; g[lane] via 4-channel reduces -------
            float g = 0.0f;
#pragma unroll 4
            for (int q = 0; q < 8; q++) {
                float v[4];
                float hv0[4], hv1[4];
#pragma unroll
                for (int r = 0; r < 4; r++) {
                    const int k = 4 * q + r;
                    const float4 w = w1c4[k];
                    float bias0 = biaskt[k][tt0];      // broadcast LDS
                    float bias1 = biaskt[k][tt1];
                    float t0 = fmaf(rz0, w.w, fmaf(ry0, w.z, fmaf(rx0, w.y, w.x)));
                    float t1 = fmaf(rz1, w.w, fmaf(ry1, w.z, fmaf(rx1, w.y, w.x)));
                    float h0 = ftanh(fmaf(s0, t0, bias0));
                    float h1 = ftanh(fmaf(s1, t1, bias1));
                    hv0[r] = h0; hv1[r] = h1;
                    if (!FULL) { h0 = v0b ? h0 : 0.0f; h1 = v1b ? h1 : 0.0f; }
                    v[r] = h0 + h1;
                }
                if (q < 4) {                           // cache channels 0..15 (128-bit)
                    *(float4*)&hc[wid][lane][4 * q] =
                        make_float4(hv0[0], hv0[1], hv0[2], hv0[3]);
                    *(float4*)&hc[wid][lane + 32][4 * q] =
                        make_float4(hv1[0], hv1[1], hv1[2], hv1[3]);
                }
                // 4-channel butterfly transpose-reduce
                {
                    const bool bb0 = lane & 1, bb1 = lane & 2;
                    float send0 = bb0 ? v[0] : v[1], keep0 = bb0 ? v[1] : v[0];
                    float a0r = keep0 + __shfl_xor_sync(FULLMASK, send0, 1);
                    float send1 = bb0 ? v[2] : v[3], keep1 = bb0 ? v[3] : v[2];
                    float a1r = keep1 + __shfl_xor_sync(FULLMASK, send1, 1);
                    float send2 = bb1 ? a0r : a1r, keep2 = bb1 ? a1r : a0r;
                    float t = keep2 + __shfl_xor_sync(FULLMASK, send2, 2);
                    t += __shfl_xor_sync(FULLMASK, t, 4);
                    t += __shfl_xor_sync(FULLMASK, t, 8);
                    t += __shfl_xor_sync(FULLMASK, t, 16);
                    if ((lane >> 2) == q) g = t;       // lane l ends with g[l]
                }
            }

            // ------------ P2: head (lane = channel) ------------------------
            gmb[wid][lane] = g * inv_m;
            __syncwarp();
            float c0a = b2k, c1a = 0.f, c2a = 0.f, c3a = 0.f;
#pragma unroll
            for (int q = 0; q < 8; q++) {
                float4 gv = gm4[q];
                c0a = fmaf(gv.x, W2s[4 * q + 0][lane], c0a);
                c1a = fmaf(gv.y, W2s[4 * q + 1][lane], c1a);
                c2a = fmaf(gv.z, W2s[4 * q + 2][lane], c2a);
                c3a = fmaf(gv.w, W2s[4 * q + 3][lane], c3a);
            }
            float h2 = ftanh((c0a + c1a) + (c2a + c3a));
            float esum = warp_sum(h2 * w3k);
            if (lane == 0) {
                int em = __ldg(&element_map[atom]);
                float Ei = esum + b3v + __ldg(&elem_bias[em]);
                outEi[atom] = Ei;
                etot += Ei;
            }
            dh2b[wid][lane] = (1.0f - h2 * h2) * w3k;
            __syncwarp();
            float dg0 = 0.f, dg1 = 0.f, dg2 = 0.f, dg3 = 0.f;
#pragma unroll
            for (int q = 0; q < 8; q++) {
                float4 dv = dh24[q];
                dg0 = fmaf(W2s[lane][4 * q + 0], dv.x, dg0);
                dg1 = fmaf(W2s[lane][4 * q + 1], dv.y, dg1);
                dg2 = fmaf(W2s[lane][4 * q + 2], dv.z, dg2);
                dg3 = fmaf(W2s[lane][4 * q + 3], dv.w, dg3);
            }
            dhb[wid][lane] = ((dg0 + dg1) + (dg2 + dg3)) * inv_m;
            __syncwarp();

            // ------------ P3: backward (lane = neighbor pair) --------------
            float f00 = 0.f, f01 = 0.f, f02 = 0.f, f03 = 0.f;
            float f10 = 0.f, f11 = 0.f, f12 = 0.f, f13 = 0.f;
#pragma unroll 2
            for (int q = 0; q < 4; q++) {          // cached channels (128-bit LDS)
                float4 dv = dh4[q];
                float4 h04 = *(const float4*)&hc[wid][lane][4 * q];
                float4 h14 = *(const float4*)&hc[wid][lane + 32][4 * q];
#pragma unroll
                for (int r = 0; r < 4; r++) {
                    const int k = 4 * q + r;
                    const float dhk = (r == 0) ? dv.x : (r == 1) ? dv.y : (r == 2) ? dv.z : dv.w;
                    const float h0 = (r == 0) ? h04.x : (r == 1) ? h04.y : (r == 2) ? h04.z : h04.w;
                    const float h1 = (r == 0) ? h14.x : (r == 1) ? h14.y : (r == 2) ? h14.z : h14.w;
                    const float4 w = w1c4[k];
                    float dp0 = dhk * fmaf(-h0, h0, 1.0f);
                    float dp1 = dhk * fmaf(-h1, h1, 1.0f);
                    f00 = fmaf(w.x, dp0, f00); f01 = fmaf(w.y, dp0, f01);
                    f02 = fmaf(w.z, dp0, f02); f03 = fmaf(w.w, dp0, f03);
                    f10 = fmaf(w.x, dp1, f10); f11 = fmaf(w.y, dp1, f11);
                    f12 = fmaf(w.z, dp1, f12); f13 = fmaf(w.w, dp1, f13);
                }
            }
#pragma unroll 2
            for (int q = 4; q < 8; q++) {          // recomputed channels
                float4 dv = dh4[q];
#pragma unroll
                for (int r = 0; r < 4; r++) {
                    const int k = 4 * q + r;
                    const float dhk = (r == 0) ? dv.x : (r == 1) ? dv.y : (r == 2) ? dv.z : dv.w;
                    const float4 w = w1c4[k];
                    float bias0 = biaskt[k][tt0];
                    float bias1 = biaskt[k][tt1];
                    float t0 = fmaf(rz0, w.w, fmaf(ry0, w.z, fmaf(rx0, w.y, w.x)));
                    float t1 = fmaf(rz1, w.w, fmaf(ry1, w.z, fmaf(rx1, w.y, w.x)));
                    float h0 = ftanh(fmaf(s0, t0, bias0));
                    float h1 = ftanh(fmaf(s1, t1, bias1));
                    float dp0 = dhk * fmaf(-h0, h0, 1.0f);
                    float dp1 = dhk * fmaf(-h1, h1, 1.0f);
                    f00 = fmaf(w.x, dp0, f00); f01 = fmaf(w.y, dp0, f01);
                    f02 = fmaf(w.z, dp0, f02); f03 = fmaf(w.w, dp0, f03);
                    f10 = fmaf(w.x, dp1, f10); f11 = fmaf(w.y, dp1, f11);
                    f12 = fmaf(w.z, dp1, f12); f13 = fmaf(w.w, dp1, f13);
                }
            }

            // ------------ epilogue per neighbor -----------------------------
            float cgx = 0.f, cgy = 0.f, cgz = 0.f;
#pragma unroll
            for (int nb = 0; nb < 2; nb++) {
                const bool valid = nb ? v1b : v0b;
                if (!valid) continue;
                const float rx = nb ? rx1 : rx0, ry = nb ? ry1 : ry0, rz = nb ? rz1 : rz0;
                const float s = nb ? s1 : s0, d = nb ? d1 : d0;
                const float ivd = nb ? ivd1 : ivd0, e = nb ? e1 : e0;
                const float fa = nb ? f10 : f00, fb = nb ? f11 : f01;
                const float fcq = nb ? f12 : f02, fd = nb ? f13 : f03;
                const int ni = nb ? ni1 : ni0;

                float fcp = (d < CUTOFF_F) ? (c1 * __sinf(d * invC)) : 0.0f;
                float ds = fa + rx * fb + ry * fcq + rz * fd;
                float dd = ds * fmaf(e, fcp, -s);  // e*(fcp - fc) = e*fcp - s
                float t2 = dd * ivd;
                float gx = fmaf(t2, rx, s * fb);
                float gy = fmaf(t2, ry, s * fcq);
                float gz = fmaf(t2, rz, s * fd);

                float pv0 = rx * gx, pv1 = rx * gy, pv2 = rx * gz;
                float pv3 = ry * gx, pv4 = ry * gy, pv5 = ry * gz;
                float pv6 = rz * gx, pv7 = rz * gy, pv8 = rz * gz;
                vir[0] += pv0; vir[1] += pv1; vir[2] += pv2;
                vir[3] += pv3; vir[4] += pv4; vir[5] += pv5;
                vir[6] += pv6; vir[7] += pv7; vir[8] += pv8;
                cgx += gx; cgy += gy; cgz += gz;

                if (ni < n) {
                    float* p = (float*)(g_scratch + ((long)bi * n + ni) * 3);
                    red_add_v4(p,     pv0, pv1, pv2, pv3);
                    red_add_v4(p + 4, pv4, pv5, pv6, pv7);
                    red_add_v4(p + 8, pv8, -gx, -gy, -gz);
                }
            }
            warp_sum3(cgx, cgy, cgz);
            if (lane == 0) {
                float* p = (float*)(g_scratch + ((long)bi * n + ai) * 3);
                red_add_v4(p + 8, 0.0f, cgx, cgy, cgz);
            }

            // incremental (bi, ai) advance
            if (++ai == n) { ai = 0; ++bi; }
        }
        flush_stats(vir, etot, cur_bi, st, lane);
    }

    // ================= device-wide barrier (ticket, monotonic) =============
    __syncthreads();
    if (tid == 0) {
        __threadfence();
        unsigned long long t = atomicAdd(&g_ctr, 1ULL);
        unsigned long long target = (t / (unsigned long long)G + 1ULL) * (unsigned long long)G;
        volatile unsigned long long* vc = (volatile unsigned long long*)&g_ctr;
        while (*vc < target) __nanosleep(128);
        __threadfence();
    }
    __syncthreads();

    // ================= pack phase (scratch -> out, then zero) ==============
    {
        const float4 z = make_float4(0.f, 0.f, 0.f, 0.f);
        const long stride = (long)G * THREADS;
        for (long i = (long)blockIdx.x * THREADS + tid; i < total; i += stride) {
            float4* r4 = &g_scratch[i * 3];
            float4 v0 = r4[0], v1 = r4[1], v2 = r4[2];
            r4[0] = z; r4[1] = z; r4[2] = z;
            float* outF  = out + b + total + i * 3;
            float* outAV = out + 10L * b + 4L * total + i * 9;
            outAV[0] = v0.x; outAV[1] = v0.y; outAV[2] = v0.z;
            outAV[3] = v0.w; outAV[4] = v1.x; outAV[5] = v1.y;
            outAV[6] = v1.z; outAV[7] = v1.w; outAV[8] = v2.x;
            outF[0] = v2.y; outF[1] = v2.z; outF[2] = v2.w;
        }
        if (blockIdx.x == 0) {
            for (int q = tid; q < b; q += THREADS) {
                out[q] = st[q]; st[q] = 0.0f;                          // Etot
            }
            for (int q = tid; q < 9 * b; q += THREADS) {
                out[b + 4L * total + q] = st[32 + q]; st[32 + q] = 0.0f; // virial
            }
        }
    }
}

// ---------------------------------------------------------------------------
extern "C" void kernel_launch(void* const* d_in, const int* in_sizes, int n_in,
                              void* d_out, int out_size) {
    const int*    element_map      = (const int*)d_in[0];
    const int*    neighbor_indices = (const int*)d_in[2];
    const int*    neighbor_types   = (const int*)d_in[3];
    const float4* neighbor_vectors = (const float4*)d_in[4];
    const float*  type_embed = (const float*)d_in[6];
    const float*  elem_bias  = (const float*)d_in[7];
    const float*  W1 = (const float*)d_in[8];
    const float*  b1 = (const float*)d_in[9];
    const float*  W2 = (const float*)d_in[10];
    const float*  b2 = (const float*)d_in[11];
    const float*  W3 = (const float*)d_in[12];
    const float*  b3 = (const float*)d_in[13];
    float* out = (float*)d_out;

    const int bn  = in_sizes[0];
    const int bnm = in_sizes[2];
    const int m   = bnm / bn;
    const int ntypes = in_sizes[7];
    int b = (int)(((long)out_size - 13L * bn) / 10L);
    if (b < 1) b = 1;
    const int n = bn / b;

    // persistent grid sized to exactly-resident occupancy (deadlock-free)
    int dev = 0;
    cudaGetDevice(&dev);
    int nsm = 0;
    cudaDeviceGetAttribute(&nsm, cudaDevAttrMultiProcessorCount, dev);
    if (nsm < 1) nsm = 148;
    int nb = 0;
    if (m == 64) {
        cudaOccupancyMaxActiveBlocksPerMultiprocessor(&nb, field_kernel<true>, THREADS, 0);
    } else {
        cudaOccupancyMaxActiveBlocksPerMultiprocessor(&nb, field_kernel<false>, THREADS, 0);
    }
    if (nb < 1) nb = 1;
    long grid = (long)nb * nsm;
    long maxBlocks = ((long)bn + NWARP - 1) / NWARP;
    if (grid > maxBlocks) grid = maxBlocks;
    if (grid < 1) grid = 1;

    if (m == 64) {
        field_kernel<true><<<(int)grid, THREADS>>>(element_map, neighbor_indices, neighbor_types,
                                                   neighbor_vectors, type_embed, elem_bias,
                                                   W1, b1, W2, b2, W3, b3, out, b, n, m, ntypes);
    } else {
        field_kernel<false><<<(int)grid, THREADS>>>(element_map, neighbor_indices, neighbor_types,
                                                    neighbor_vectors, type_embed, elem_bias,
                                                    W1, b1, W2, b2, W3, b3, out, b, n, m, ntypes);
    }
}

// round 16
// speedup vs baseline: 1.0826x; 1.0018x over previous
#include <cuda_runtime.h>
#include <math.h>

#define DD 32
#define NWARP 4
#define THREADS (NWARP * 32)
#define CUTOFF_F 6.0f
#define PI_F 3.14159265358979323846f
#define FULLMASK 0xffffffffu

// rows: 12 floats (3 x float4) per (batch,atom): [pv0..pv8, fx, fy, fz]
// stats tail (at float offset bn*12): [Etot(b)..., pad to 32, virial(9b)...]
// Zero at module load; the in-kernel pack phase re-zeroes everything it
// reads, so scratch is zero at every kernel_launch entry (deterministic).
__device__ float4 g_scratch[32768 * 3 + 64];
// monotonic device-wide barrier counter (never reset; generation = t/G)
__device__ unsigned long long g_ctr = 0ULL;

// ---------------------------------------------------------------------------
__device__ __forceinline__ float ftanh(float x) {
    float y;
    asm("tanh.approx.f32 %0, %1;" : "=f"(y) : "f"(x));
    return y;
}
__device__ __forceinline__ float warp_sum(float v) {
#pragma unroll
    for (int o = 16; o; o >>= 1) v += __shfl_xor_sync(FULLMASK, v, o);
    return v;
}
__device__ __forceinline__ void red_add_v4(float* p, float a, float b, float c, float d) {
    asm volatile("red.global.add.v4.f32 [%0], {%1,%2,%3,%4};"
                 :: "l"(p), "f"(a), "f"(b), "f"(c), "f"(d) : "memory");
}
__device__ __forceinline__ void flush_stats(float (&vir)[9], float& etot, int cur_bi,
                                            float* __restrict__ st, int lane) {
    float tv[9];
#pragma unroll
    for (int q = 0; q < 9; q++) { tv[q] = warp_sum(vir[q]); vir[q] = 0.0f; }
    if (lane == 0) {
#pragma unroll
        for (int q = 0; q < 9; q++) atomicAdd(&st[32 + cur_bi * 9 + q], tv[q]);
        atomicAdd(&st[cur_bi], etot);
    }
    etot = 0.0f;
}

// ---------------------------------------------------------------------------
// Persistent warp-per-atom kernel + device-wide barrier + in-kernel pack.
// Lane owns neighbors (lane, lane+32). h cached in smem for channels 0..15
// via 128-bit STS/LDS (20-float row stride, conflict-free), recomputed in
// backward for 16..31. Next atom's inputs software-prefetched; bias via
// scalar broadcast LDS. NO min-blocks cap: kernel wants ~96 regs (caps spill).
// ---------------------------------------------------------------------------
template<bool FULL>
__global__ __launch_bounds__(THREADS) void field_kernel(
    const int* __restrict__ element_map,
    const int* __restrict__ neighbor_indices,
    const int* __restrict__ neighbor_types,
    const float4* __restrict__ neighbor_vectors,
    const float* __restrict__ type_embed,
    const float* __restrict__ elem_bias,
    const float* __restrict__ W1, const float* __restrict__ b1,
    const float* __restrict__ W2, const float* __restrict__ b2,
    const float* __restrict__ W3, const float* __restrict__ b3,
    float* __restrict__ out,
    int b, int n, int m, int ntypes)
{
    __shared__ __align__(16) float4 w1c4[DD];     // (W1[0][k],W1[1][k],W1[2][k],W1[3][k])
    __shared__ __align__(16) float biaskt[DD][4]; // [k][tt]: b1[k]+type_embed[tt][k]
    __shared__ float W2s[DD][DD + 1];
    __shared__ float b2s[DD], W3s[DD];
    __shared__ __align__(16) float gmb[NWARP][DD];
    __shared__ __align__(16) float dh2b[NWARP][DD];
    __shared__ __align__(16) float dhb[NWARP][DD];
    // h for channels 0..15: [warp][neighbor j][16 channels + 4 pad]
    __shared__ __align__(16) float hc[NWARP][64][20];

    const int tid  = threadIdx.x;
    const int lane = tid & 31;
    const int wid  = tid >> 5;

    for (int idx = tid; idx < DD * DD; idx += THREADS)
        W2s[idx >> 5][idx & 31] = W2[idx];
    if (tid < DD) {
        w1c4[tid] = make_float4(W1[tid], W1[DD + tid], W1[2 * DD + tid], W1[3 * DD + tid]);
        float bb = b1[tid];
        biaskt[tid][0] = bb + type_embed[tid];
        biaskt[tid][1] = (ntypes > 1) ? bb + type_embed[DD + tid] : 0.0f;
        biaskt[tid][2] = (ntypes > 2) ? bb + type_embed[2 * DD + tid] : 0.0f;
        biaskt[tid][3] = 0.0f;
        b2s[tid] = b2[tid];
        W3s[tid] = W3[tid];
    }
    __syncthreads();

    const float b2k = b2s[lane], w3k = W3s[lane];
    const float b3v = __ldg(b3);
    const float invC = PI_F / CUTOFF_F;
    const float c1 = -0.5f * invC;
    const float inv_m = 1.0f / (float)m;

    const long total = (long)b * n;
    float* outEi = out + b;
    float* st = (float*)g_scratch + total * 12;

    const int  G = gridDim.x;
    const long nwarps = (long)G * NWARP;
    const long apw = (total + nwarps - 1) / nwarps;
    const long gw = (long)blockIdx.x * NWARP + wid;
    long a0 = gw * apw;
    long a1 = a0 + apw; if (a1 > total) a1 = total;

    const bool v0b = FULL || (lane < m);
    const bool v1b = FULL || (lane + 32 < m);

    if (a0 < total) {
        float vir[9];
#pragma unroll
        for (int q = 0; q < 9; q++) vir[q] = 0.0f;
        float etot = 0.0f;

        const float4* gm4  = (const float4*)gmb[wid];
        const float4* dh24 = (const float4*)dh2b[wid];
        const float4* dh4  = (const float4*)dhb[wid];

        int cur_bi = -1;

        // ---- prefetch state for atom a0 ----
        float4 pnv0 = make_float4(0,0,0,0), pnv1 = make_float4(0,0,0,0);
        int pni0 = 0x7fffffff, pni1 = 0x7fffffff, ptt0 = 3, ptt1 = 3;
        {
            const long base = a0 * m + lane;
            if (v0b) {
                pnv0 = __ldg(&neighbor_vectors[base]);
                pni0 = __ldg(&neighbor_indices[base]);
                ptt0 = __ldg(&neighbor_types[base]);
            }
            if (v1b) {
                pnv1 = __ldg(&neighbor_vectors[base + 32]);
                pni1 = __ldg(&neighbor_indices[base + 32]);
                ptt1 = __ldg(&neighbor_types[base + 32]);
            }
        }

        for (long atom = a0; atom < a1; ++atom) {
            const int bi = (int)(atom / n);
            const int ai = (int)(atom - (long)bi * n);
            if (bi != cur_bi) {
                if (cur_bi >= 0) flush_stats(vir, etot, cur_bi, st, lane);
                cur_bi = bi;
            }

            // ------------ P0: consume prefetched inputs --------------------
            const float rx0 = pnv0.y, ry0 = pnv0.z, rz0 = pnv0.w;
            const float rx1 = pnv1.y, ry1 = pnv1.z, rz1 = pnv1.w;
            const int tt0 = ptt0, tt1 = ptt1, ni0 = pni0, ni1 = pni1;
            float s0 = 0.f, d0 = 0.f, ivd0 = 0.f, e0 = 0.f;
            float s1 = 0.f, d1 = 0.f, ivd1 = 0.f, e1 = 0.f;
            if (v0b) {
                float r2 = rx0 * rx0 + ry0 * ry0 + rz0 * rz0;
                ivd0 = rsqrtf(r2);
                d0 = r2 * ivd0;
                float fc = 0.5f * (__cosf(fminf(d0, CUTOFF_F) * invC) + 1.0f);
                e0 = __expf(-d0);
                s0 = e0 * fc;
            }
            if (v1b) {
                float r2 = rx1 * rx1 + ry1 * ry1 + rz1 * rz1;
                ivd1 = rsqrtf(r2);
                d1 = r2 * ivd1;
                float fc = 0.5f * (__cosf(fminf(d1, CUTOFF_F) * invC) + 1.0f);
                e1 = __expf(-d1);
                s1 = e1 * fc;
            }

            // ---- prefetch next atom's inputs (hidden behind P1..P3) -------
            if (atom + 1 < a1) {
                const long base = (atom + 1) * m + lane;
                if (v0b) {
                    pnv0 = __ldg(&neighbor_vectors[base]);
                    pni0 = __ldg(&neighbor_indices[base]);
                    ptt0 = __ldg(&neighbor_types[base]);
                }
                if (v1b) {
                    pnv1 = __ldg(&neighbor_vectors[base + 32]);
                    pni1 = __ldg(&neighbor_indices[base + 32]);
                    ptt1 = __ldg(&neighbor_types[base + 32]);
                }
            }

            // ------------ P1: forward; g[lane] via 4-channel reduces -------
            float g = 0.0f;
#pragma unroll 4
            for (int q = 0; q < 8; q++) {
                float v[4];
                float hv0[4], hv1[4];
#pragma unroll
                for (int r = 0; r < 4; r++) {
                    const int k = 4 * q + r;
                    const float4 w = w1c4[k];
                    float bias0 = biaskt[k][tt0];      // broadcast LDS
                    float bias1 = biaskt[k][tt1];
                    float t0 = fmaf(rz0, w.w, fmaf(ry0, w.z, fmaf(rx0, w.y, w.x)));
                    float t1 = fmaf(rz1, w.w, fmaf(ry1, w.z, fmaf(rx1, w.y, w.x)));
                    float h0 = ftanh(fmaf(s0, t0, bias0));
                    float h1 = ftanh(fmaf(s1, t1, bias1));
                    hv0[r] = h0; hv1[r] = h1;
                    if (!FULL) { h0 = v0b ? h0 : 0.0f; h1 = v1b ? h1 : 0.0f; }
                    v[r] = h0 + h1;
                }
                if (q < 4) {                           // cache channels 0..15 (128-bit)
                    *(float4*)&hc[wid][lane][4 * q] =
                        make_float4(hv0[0], hv0[1], hv0[2], hv0[3]);
                    *(float4*)&hc[wid][lane + 32][4 * q] =
                        make_float4(hv1[0], hv1[1], hv1[2], hv1[3]);
                }
                // 4-channel butterfly transpose-reduce
                {
                    const bool bb0 = lane & 1, bb1 = lane & 2;
                    float send0 = bb0 ? v[0] : v[1], keep0 = bb0 ? v[1] : v[0];
                    float a0r = keep0 + __shfl_xor_sync(FULLMASK, send0, 1);
                    float send1 = bb0 ? v[2] : v[3], keep1 = bb0 ? v[3] : v[2];
                    float a1r = keep1 + __shfl_xor_sync(FULLMASK, send1, 1);
                    float send2 = bb1 ? a0r : a1r, keep2 = bb1 ? a1r : a0r;
                    float t = keep2 + __shfl_xor_sync(FULLMASK, send2, 2);
                    t += __shfl_xor_sync(FULLMASK, t, 4);
                    t += __shfl_xor_sync(FULLMASK, t, 8);
                    t += __shfl_xor_sync(FULLMASK, t, 16);
                    if ((lane >> 2) == q) g = t;       // lane l ends with g[l]
                }
            }

            // ------------ P2: head (lane = channel) ------------------------
            gmb[wid][lane] = g * inv_m;
            __syncwarp();
            float c0a = b2k, c1a = 0.f, c2a = 0.f, c3a = 0.f;
#pragma unroll
            for (int q = 0; q < 8; q++) {
                float4 gv = gm4[q];
                c0a = fmaf(gv.x, W2s[4 * q + 0][lane], c0a);
                c1a = fmaf(gv.y, W2s[4 * q + 1][lane], c1a);
                c2a = fmaf(gv.z, W2s[4 * q + 2][lane], c2a);
                c3a = fmaf(gv.w, W2s[4 * q + 3][lane], c3a);
            }
            float h2 = ftanh((c0a + c1a) + (c2a + c3a));
            float esum = warp_sum(h2 * w3k);
            if (lane == 0) {
                int em = __ldg(&element_map[atom]);
                float Ei = esum + b3v + __ldg(&elem_bias[em]);
                outEi[atom] = Ei;
                etot += Ei;
            }
            dh2b[wid][lane] = (1.0f - h2 * h2) * w3k;
            __syncwarp();
            float dg0 = 0.f, dg1 = 0.f, dg2 = 0.f, dg3 = 0.f;
#pragma unroll
            for (int q = 0; q < 8; q++) {
                float4 dv = dh24[q];
                dg0 = fmaf(W2s[lane][4 * q + 0], dv.x, dg0);
                dg1 = fmaf(W2s[lane][4 * q + 1], dv.y, dg1);
                dg2 = fmaf(W2s[lane][4 * q + 2], dv.z, dg2);
                dg3 = fmaf(W2s[lane][4 * q + 3], dv.w, dg3);
            }
            dhb[wid][lane] = ((dg0 + dg1) + (dg2 + dg3)) * inv_m;
            __syncwarp();

            // ------------ P3: backward (lane = neighbor pair) --------------
            float f00 = 0.f, f01 = 0.f, f02 = 0.f, f03 = 0.f;
            float f10 = 0.f, f11 = 0.f, f12 = 0.f, f13 = 0.f;
#pragma unroll 2
            for (int q = 0; q < 4; q++) {          // cached channels (128-bit LDS)
                float4 dv = dh4[q];
                float4 h04 = *(const float4*)&hc[wid][lane][4 * q];
                float4 h14 = *(const float4*)&hc[wid][lane + 32][4 * q];
#pragma unroll
                for (int r = 0; r < 4; r++) {
                    const int k = 4 * q + r;
                    const float dhk = (r == 0) ? dv.x : (r == 1) ? dv.y : (r == 2) ? dv.z : dv.w;
                    const float h0 = (r == 0) ? h04.x : (r == 1) ? h04.y : (r == 2) ? h04.z : h04.w;
                    const float h1 = (r == 0) ? h14.x : (r == 1) ? h14.y : (r == 2) ? h14.z : h14.w;
                    const float4 w = w1c4[k];
                    float dp0 = dhk * fmaf(-h0, h0, 1.0f);
                    float dp1 = dhk * fmaf(-h1, h1, 1.0f);
                    f00 = fmaf(w.x, dp0, f00); f01 = fmaf(w.y, dp0, f01);
                    f02 = fmaf(w.z, dp0, f02); f03 = fmaf(w.w, dp0, f03);
                    f10 = fmaf(w.x, dp1, f10); f11 = fmaf(w.y, dp1, f11);
                    f12 = fmaf(w.z, dp1, f12); f13 = fmaf(w.w, dp1, f13);
                }
            }
#pragma unroll 2
            for (int q = 4; q < 8; q++) {          // recomputed channels
                float4 dv = dh4[q];
#pragma unroll
                for (int r = 0; r < 4; r++) {
                    const int k = 4 * q + r;
                    const float dhk = (r == 0) ? dv.x : (r == 1) ? dv.y : (r == 2) ? dv.z : dv.w;
                    const float4 w = w1c4[k];
                    float bias0 = biaskt[k][tt0];
                    float bias1 = biaskt[k][tt1];
                    float t0 = fmaf(rz0, w.w, fmaf(ry0, w.z, fmaf(rx0, w.y, w.x)));
                    float t1 = fmaf(rz1, w.w, fmaf(ry1, w.z, fmaf(rx1, w.y, w.x)));
                    float h0 = ftanh(fmaf(s0, t0, bias0));
                    float h1 = ftanh(fmaf(s1, t1, bias1));
                    float dp0 = dhk * fmaf(-h0, h0, 1.0f);
                    float dp1 = dhk * fmaf(-h1, h1, 1.0f);
                    f00 = fmaf(w.x, dp0, f00); f01 = fmaf(w.y, dp0, f01);
                    f02 = fmaf(w.z, dp0, f02); f03 = fmaf(w.w, dp0, f03);
                    f10 = fmaf(w.x, dp1, f10); f11 = fmaf(w.y, dp1, f11);
                    f12 = fmaf(w.z, dp1, f12); f13 = fmaf(w.w, dp1, f13);
                }
            }

            // ------------ epilogue per neighbor -----------------------------
            float cgx = 0.f, cgy = 0.f, cgz = 0.f;
#pragma unroll
            for (int nb = 0; nb < 2; nb++) {
                const bool valid = nb ? v1b : v0b;
                if (!valid) continue;
                const float rx = nb ? rx1 : rx0, ry = nb ? ry1 : ry0, rz = nb ? rz1 : rz0;
                const float s = nb ? s1 : s0, d = nb ? d1 : d0;
                const float ivd = nb ? ivd1 : ivd0, e = nb ? e1 : e0;
                const float fa = nb ? f10 : f00, fb = nb ? f11 : f01;
                const float fcq = nb ? f12 : f02, fd = nb ? f13 : f03;
                const int ni = nb ? ni1 : ni0;

                float fcp = (d < CUTOFF_F) ? (c1 * __sinf(d * invC)) : 0.0f;
                float ds = fa + rx * fb + ry * fcq + rz * fd;
                float dd = ds * fmaf(e, fcp, -s);  // e*(fcp - fc) = e*fcp - s
                float t2 = dd * ivd;
                float gx = fmaf(t2, rx, s * fb);
                float gy = fmaf(t2, ry, s * fcq);
                float gz = fmaf(t2, rz, s * fd);

                float pv0 = rx * gx, pv1 = rx * gy, pv2 = rx * gz;
                float pv3 = ry * gx, pv4 = ry * gy, pv5 = ry * gz;
                float pv6 = rz * gx, pv7 = rz * gy, pv8 = rz * gz;
                vir[0] += pv0; vir[1] += pv1; vir[2] += pv2;
                vir[3] += pv3; vir[4] += pv4; vir[5] += pv5;
                vir[6] += pv6; vir[7] += pv7; vir[8] += pv8;
                cgx += gx; cgy += gy; cgz += gz;

                if (ni < n) {
                    float* p = (float*)(g_scratch + ((long)bi * n + ni) * 3);
                    red_add_v4(p,     pv0, pv1, pv2, pv3);
                    red_add_v4(p + 4, pv4, pv5, pv6, pv7);
                    red_add_v4(p + 8, pv8, -gx, -gy, -gz);
                }
            }
            float cx = warp_sum(cgx), cy = warp_sum(cgy), cz = warp_sum(cgz);
            if (lane == 0) {
                float* p = (float*)(g_scratch + ((long)bi * n + ai) * 3);
                red_add_v4(p + 8, 0.0f, cx, cy, cz);
            }
        }
        if (cur_bi >= 0) flush_stats(vir, etot, cur_bi, st, lane);
    }

    // ================= device-wide barrier (ticket, monotonic) =============
    __syncthreads();
    if (tid == 0) {
        __threadfence();
        unsigned long long t = atomicAdd(&g_ctr, 1ULL);
        unsigned long long target = (t / (unsigned long long)G + 1ULL) * (unsigned long long)G;
        volatile unsigned long long* vc = (volatile unsigned long long*)&g_ctr;
        while (*vc < target) __nanosleep(128);
        __threadfence();
    }
    __syncthreads();

    // ================= pack phase (scratch -> out, then zero) ==============
    {
        const float4 z = make_float4(0.f, 0.f, 0.f, 0.f);
        const long stride = (long)G * THREADS;
        for (long i = (long)blockIdx.x * THREADS + tid; i < total; i += stride) {
            float4* r4 = &g_scratch[i * 3];
            float4 v0 = r4[0], v1 = r4[1], v2 = r4[2];
            r4[0] = z; r4[1] = z; r4[2] = z;
            float* outF  = out + b + total + i * 3;
            float* outAV = out + 10L * b + 4L * total + i * 9;
            outAV[0] = v0.x; outAV[1] = v0.y; outAV[2] = v0.z;
            outAV[3] = v0.w; outAV[4] = v1.x; outAV[5] = v1.y;
            outAV[6] = v1.z; outAV[7] = v1.w; outAV[8] = v2.x;
            outF[0] = v2.y; outF[1] = v2.z; outF[2] = v2.w;
        }
        if (blockIdx.x == 0) {
            for (int q = tid; q < b; q += THREADS) {
                out[q] = st[q]; st[q] = 0.0f;                          // Etot
            }
            for (int q = tid; q < 9 * b; q += THREADS) {
                out[b + 4L * total + q] = st[32 + q]; st[32 + q] = 0.0f; // virial
            }
        }
    }
}

// ---------------------------------------------------------------------------
extern "C" void kernel_launch(void* const* d_in, const int* in_sizes, int n_in,
                              void* d_out, int out_size) {
    const int*    element_map      = (const int*)d_in[0];
    const int*    neighbor_indices = (const int*)d_in[2];
    const int*    neighbor_types   = (const int*)d_in[3];
    const float4* neighbor_vectors = (const float4*)d_in[4];
    const float*  type_embed = (const float*)d_in[6];
    const float*  elem_bias  = (const float*)d_in[7];
    const float*  W1 = (const float*)d_in[8];
    const float*  b1 = (const float*)d_in[9];
    const float*  W2 = (const float*)d_in[10];
    const float*  b2 = (const float*)d_in[11];
    const float*  W3 = (const float*)d_in[12];
    const float*  b3 = (const float*)d_in[13];
    float* out = (float*)d_out;

    const int bn  = in_sizes[0];
    const int bnm = in_sizes[2];
    const int m   = bnm / bn;
    const int ntypes = in_sizes[7];
    int b = (int)(((long)out_size - 13L * bn) / 10L);
    if (b < 1) b = 1;
    const int n = bn / b;

    // persistent grid sized to exactly-resident occupancy (deadlock-free)
    int dev = 0;
    cudaGetDevice(&dev);
    int nsm = 0;
    cudaDeviceGetAttribute(&nsm, cudaDevAttrMultiProcessorCount, dev);
    if (nsm < 1) nsm = 148;
    int nb = 0;
    if (m == 64) {
        cudaOccupancyMaxActiveBlocksPerMultiprocessor(&nb, field_kernel<true>, THREADS, 0);
    } else {
        cudaOccupancyMaxActiveBlocksPerMultiprocessor(&nb, field_kernel<false>, THREADS, 0);
    }
    if (nb < 1) nb = 1;
    long grid = (long)nb * nsm;
    long maxBlocks = ((long)bn + NWARP - 1) / NWARP;
    if (grid > maxBlocks) grid = maxBlocks;
    if (grid < 1) grid = 1;

    if (m == 64) {
        field_kernel<true><<<(int)grid, THREADS>>>(element_map, neighbor_indices, neighbor_types,
                                                   neighbor_vectors, type_embed, elem_bias,
                                                   W1, b1, W2, b2, W3, b3, out, b, n, m, ntypes);
    } else {
        field_kernel<false><<<(int)grid, THREADS>>>(element_map, neighbor_indices, neighbor_types,
                                                    neighbor_vectors, type_embed, elem_bias,
                                                    W1, b1, W2, b2, W3, b3, out, b, n, m, ntypes);
    }
}

// round 17
// speedup vs baseline: 1.1460x; 1.0586x over previous
#include <cuda_runtime.h>
#include <math.h>

#define DD 32
#define NWARP 4
#define THREADS (NWARP * 32)
#define CUTOFF_F 6.0f
#define PI_F 3.14159265358979323846f
#define FULLMASK 0xffffffffu

// rows: 12 floats (3 x float4) per (batch,atom): [pv0..pv8, fx, fy, fz]
// stats tail (at float offset bn*12): [Etot(b)..., pad to 32, virial(9b)...]
// Zero at module load; the in-kernel pack phase re-zeroes everything it
// reads, so scratch is zero at every kernel_launch entry (deterministic).
__device__ float4 g_scratch[32768 * 3 + 64];
// monotonic device-wide barrier counter (never reset; generation = t/G)
__device__ unsigned long long g_ctr = 0ULL;

// ---------------------------------------------------------------------------
__device__ __forceinline__ float ftanh(float x) {
    float y;
    asm("tanh.approx.f32 %0, %1;" : "=f"(y) : "f"(x));
    return y;
}
__device__ __forceinline__ float warp_sum(float v) {
#pragma unroll
    for (int o = 16; o; o >>= 1) v += __shfl_xor_sync(FULLMASK, v, o);
    return v;
}
__device__ __forceinline__ void red_add_v4(float* p, float a, float b, float c, float d) {
    asm volatile("red.global.add.v4.f32 [%0], {%1,%2,%3,%4};"
                 :: "l"(p), "f"(a), "f"(b), "f"(c), "f"(d) : "memory");
}
__device__ __forceinline__ void flush_stats(float (&vir)[9], float& etot, int cur_bi,
                                            float* __restrict__ st, int lane) {
    float tv[9];
#pragma unroll
    for (int q = 0; q < 9; q++) { tv[q] = warp_sum(vir[q]); vir[q] = 0.0f; }
    if (lane == 0) {
#pragma unroll
        for (int q = 0; q < 9; q++) atomicAdd(&st[32 + cur_bi * 9 + q], tv[q]);
        atomicAdd(&st[cur_bi], etot);
    }
    etot = 0.0f;
}

// ---------------------------------------------------------------------------
// Persistent warp-per-atom kernel + device-wide barrier + in-kernel pack.
// Lane owns neighbors (lane, lane+32). h cached in smem for channels 0..15
// via 128-bit STS/LDS (20-float row stride, conflict-free), recomputed in
// backward for 16..31. Next atom's inputs software-prefetched; bias via
// scalar broadcast LDS. NO min-blocks cap: kernel wants ~96 regs (caps spill).
// fcp (cutoff-derivative sin term) hoisted into P0.
// ---------------------------------------------------------------------------
template<bool FULL>
__global__ __launch_bounds__(THREADS) void field_kernel(
    const int* __restrict__ element_map,
    const int* __restrict__ neighbor_indices,
    const int* __restrict__ neighbor_types,
    const float4* __restrict__ neighbor_vectors,
    const float* __restrict__ type_embed,
    const float* __restrict__ elem_bias,
    const float* __restrict__ W1, const float* __restrict__ b1,
    const float* __restrict__ W2, const float* __restrict__ b2,
    const float* __restrict__ W3, const float* __restrict__ b3,
    float* __restrict__ out,
    int b, int n, int m, int ntypes)
{
    __shared__ __align__(16) float4 w1c4[DD];     // (W1[0][k],W1[1][k],W1[2][k],W1[3][k])
    __shared__ __align__(16) float biaskt[DD][4]; // [k][tt]: b1[k]+type_embed[tt][k]
    __shared__ float W2s[DD][DD + 1];
    __shared__ float b2s[DD], W3s[DD];
    __shared__ __align__(16) float gmb[NWARP][DD];
    __shared__ __align__(16) float dh2b[NWARP][DD];
    __shared__ __align__(16) float dhb[NWARP][DD];
    // h for channels 0..15: [warp][neighbor j][16 channels + 4 pad]
    __shared__ __align__(16) float hc[NWARP][64][20];

    const int tid  = threadIdx.x;
    const int lane = tid & 31;
    const int wid  = tid >> 5;

    for (int idx = tid; idx < DD * DD; idx += THREADS)
        W2s[idx >> 5][idx & 31] = W2[idx];
    if (tid < DD) {
        w1c4[tid] = make_float4(W1[tid], W1[DD + tid], W1[2 * DD + tid], W1[3 * DD + tid]);
        float bb = b1[tid];
        biaskt[tid][0] = bb + type_embed[tid];
        biaskt[tid][1] = (ntypes > 1) ? bb + type_embed[DD + tid] : 0.0f;
        biaskt[tid][2] = (ntypes > 2) ? bb + type_embed[2 * DD + tid] : 0.0f;
        biaskt[tid][3] = 0.0f;
        b2s[tid] = b2[tid];
        W3s[tid] = W3[tid];
    }
    __syncthreads();

    const float b2k = b2s[lane], w3k = W3s[lane];
    const float b3v = __ldg(b3);
    const float invC = PI_F / CUTOFF_F;
    const float c1 = -0.5f * invC;
    const float inv_m = 1.0f / (float)m;

    const long total = (long)b * n;
    float* outEi = out + b;
    float* st = (float*)g_scratch + total * 12;

    const int  G = gridDim.x;
    const long nwarps = (long)G * NWARP;
    const long apw = (total + nwarps - 1) / nwarps;
    const long gw = (long)blockIdx.x * NWARP + wid;
    long a0 = gw * apw;
    long a1 = a0 + apw; if (a1 > total) a1 = total;

    const bool v0b = FULL || (lane < m);
    const bool v1b = FULL || (lane + 32 < m);

    if (a0 < total) {
        float vir[9];
#pragma unroll
        for (int q = 0; q < 9; q++) vir[q] = 0.0f;
        float etot = 0.0f;

        const float4* gm4  = (const float4*)gmb[wid];
        const float4* dh24 = (const float4*)dh2b[wid];
        const float4* dh4  = (const float4*)dhb[wid];

        int cur_bi = -1;

        // ---- prefetch state for atom a0 ----
        float4 pnv0 = make_float4(0,0,0,0), pnv1 = make_float4(0,0,0,0);
        int pni0 = 0x7fffffff, pni1 = 0x7fffffff, ptt0 = 3, ptt1 = 3;
        {
            const long base = a0 * m + lane;
            if (v0b) {
                pnv0 = __ldg(&neighbor_vectors[base]);
                pni0 = __ldg(&neighbor_indices[base]);
                ptt0 = __ldg(&neighbor_types[base]);
            }
            if (v1b) {
                pnv1 = __ldg(&neighbor_vectors[base + 32]);
                pni1 = __ldg(&neighbor_indices[base + 32]);
                ptt1 = __ldg(&neighbor_types[base + 32]);
            }
        }

        for (long atom = a0; atom < a1; ++atom) {
            const int bi = (int)(atom / n);
            const int ai = (int)(atom - (long)bi * n);
            if (bi != cur_bi) {
                if (cur_bi >= 0) flush_stats(vir, etot, cur_bi, st, lane);
                cur_bi = bi;
            }

            // ------------ P0: consume prefetched inputs --------------------
            // fcp = d<C ? -0.5*(pi/C)*sin(d*pi/C) : 0  computed here (not epilogue)
            const float rx0 = pnv0.y, ry0 = pnv0.z, rz0 = pnv0.w;
            const float rx1 = pnv1.y, ry1 = pnv1.z, rz1 = pnv1.w;
            const int tt0 = ptt0, tt1 = ptt1, ni0 = pni0, ni1 = pni1;
            float s0 = 0.f, ivd0 = 0.f, e0 = 0.f, fcp0 = 0.f;
            float s1 = 0.f, ivd1 = 0.f, e1 = 0.f, fcp1 = 0.f;
            if (v0b) {
                float r2 = rx0 * rx0 + ry0 * ry0 + rz0 * rz0;
                ivd0 = rsqrtf(r2);
                float d = r2 * ivd0;
                float fc = 0.5f * (__cosf(fminf(d, CUTOFF_F) * invC) + 1.0f);
                e0 = __expf(-d);
                s0 = e0 * fc;
                fcp0 = (d < CUTOFF_F) ? (c1 * __sinf(d * invC)) : 0.0f;
            }
            if (v1b) {
                float r2 = rx1 * rx1 + ry1 * ry1 + rz1 * rz1;
                ivd1 = rsqrtf(r2);
                float d = r2 * ivd1;
                float fc = 0.5f * (__cosf(fminf(d, CUTOFF_F) * invC) + 1.0f);
                e1 = __expf(-d);
                s1 = e1 * fc;
                fcp1 = (d < CUTOFF_F) ? (c1 * __sinf(d * invC)) : 0.0f;
            }

            // ---- prefetch next atom's inputs (hidden behind P1..P3) -------
            if (atom + 1 < a1) {
                const long base = (atom + 1) * m + lane;
                if (v0b) {
                    pnv0 = __ldg(&neighbor_vectors[base]);
                    pni0 = __ldg(&neighbor_indices[base]);
                    ptt0 = __ldg(&neighbor_types[base]);
                }
                if (v1b) {
                    pnv1 = __ldg(&neighbor_vectors[base + 32]);
                    pni1 = __ldg(&neighbor_indices[base + 32]);
                    ptt1 = __ldg(&neighbor_types[base + 32]);
                }
            }

            // ------------ P1: forward; g[lane] via 4-channel reduces -------
            float g = 0.0f;
#pragma unroll
            for (int q = 0; q < 8; q++) {
                float v[4];
                float hv0[4], hv1[4];
#pragma unroll
                for (int r = 0; r < 4; r++) {
                    const int k = 4 * q + r;
                    const float4 w = w1c4[k];
                    float bias0 = biaskt[k][tt0];      // broadcast LDS
                    float bias1 = biaskt[k][tt1];
                    float t0 = fmaf(rz0, w.w, fmaf(ry0, w.z, fmaf(rx0, w.y, w.x)));
                    float t1 = fmaf(rz1, w.w, fmaf(ry1, w.z, fmaf(rx1, w.y, w.x)));
                    float h0 = ftanh(fmaf(s0, t0, bias0));
                    float h1 = ftanh(fmaf(s1, t1, bias1));
                    hv0[r] = h0; hv1[r] = h1;
                    if (!FULL) { h0 = v0b ? h0 : 0.0f; h1 = v1b ? h1 : 0.0f; }
                    v[r] = h0 + h1;
                }
                if (q < 4) {                           // cache channels 0..15 (128-bit)
                    *(float4*)&hc[wid][lane][4 * q] =
                        make_float4(hv0[0], hv0[1], hv0[2], hv0[3]);
                    *(float4*)&hc[wid][lane + 32][4 * q] =
                        make_float4(hv1[0], hv1[1], hv1[2], hv1[3]);
                }
                // 4-channel butterfly transpose-reduce
                {
                    const bool bb0 = lane & 1, bb1 = lane & 2;
                    float send0 = bb0 ? v[0] : v[1], keep0 = bb0 ? v[1] : v[0];
                    float a0r = keep0 + __shfl_xor_sync(FULLMASK, send0, 1);
                    float send1 = bb0 ? v[2] : v[3], keep1 = bb0 ? v[3] : v[2];
                    float a1r = keep1 + __shfl_xor_sync(FULLMASK, send1, 1);
                    float send2 = bb1 ? a0r : a1r, keep2 = bb1 ? a1r : a0r;
                    float t = keep2 + __shfl_xor_sync(FULLMASK, send2, 2);
                    t += __shfl_xor_sync(FULLMASK, t, 4);
                    t += __shfl_xor_sync(FULLMASK, t, 8);
                    t += __shfl_xor_sync(FULLMASK, t, 16);
                    if ((lane >> 2) == q) g = t;       // lane l ends with g[l]
                }
            }

            // ------------ P2: head (lane = channel) ------------------------
            gmb[wid][lane] = g * inv_m;
            __syncwarp();
            float c0a = b2k, c1a = 0.f, c2a = 0.f, c3a = 0.f;
#pragma unroll
            for (int q = 0; q < 8; q++) {
                float4 gv = gm4[q];
                c0a = fmaf(gv.x, W2s[4 * q + 0][lane], c0a);
                c1a = fmaf(gv.y, W2s[4 * q + 1][lane], c1a);
                c2a = fmaf(gv.z, W2s[4 * q + 2][lane], c2a);
                c3a = fmaf(gv.w, W2s[4 * q + 3][lane], c3a);
            }
            float h2 = ftanh((c0a + c1a) + (c2a + c3a));
            float esum = warp_sum(h2 * w3k);
            if (lane == 0) {
                int em = __ldg(&element_map[atom]);
                float Ei = esum + b3v + __ldg(&elem_bias[em]);
                outEi[atom] = Ei;
                etot += Ei;
            }
            dh2b[wid][lane] = (1.0f - h2 * h2) * w3k;
            __syncwarp();
            float dg0 = 0.f, dg1 = 0.f, dg2 = 0.f, dg3 = 0.f;
#pragma unroll
            for (int q = 0; q < 8; q++) {
                float4 dv = dh24[q];
                dg0 = fmaf(W2s[lane][4 * q + 0], dv.x, dg0);
                dg1 = fmaf(W2s[lane][4 * q + 1], dv.y, dg1);
                dg2 = fmaf(W2s[lane][4 * q + 2], dv.z, dg2);
                dg3 = fmaf(W2s[lane][4 * q + 3], dv.w, dg3);
            }
            dhb[wid][lane] = ((dg0 + dg1) + (dg2 + dg3)) * inv_m;
            __syncwarp();

            // ------------ P3: backward (lane = neighbor pair) --------------
            float f00 = 0.f, f01 = 0.f, f02 = 0.f, f03 = 0.f;
            float f10 = 0.f, f11 = 0.f, f12 = 0.f, f13 = 0.f;
#pragma unroll
            for (int q = 0; q < 4; q++) {          // cached channels (128-bit LDS)
                float4 dv = dh4[q];
                float4 h04 = *(const float4*)&hc[wid][lane][4 * q];
                float4 h14 = *(const float4*)&hc[wid][lane + 32][4 * q];
#pragma unroll
                for (int r = 0; r < 4; r++) {
                    const int k = 4 * q + r;
                    const float dhk = (r == 0) ? dv.x : (r == 1) ? dv.y : (r == 2) ? dv.z : dv.w;
                    const float h0 = (r == 0) ? h04.x : (r == 1) ? h04.y : (r == 2) ? h04.z : h04.w;
                    const float h1 = (r == 0) ? h14.x : (r == 1) ? h14.y : (r == 2) ? h14.z : h14.w;
                    const float4 w = w1c4[k];
                    float dp0 = dhk * fmaf(-h0, h0, 1.0f);
                    float dp1 = dhk * fmaf(-h1, h1, 1.0f);
                    f00 = fmaf(w.x, dp0, f00); f01 = fmaf(w.y, dp0, f01);
                    f02 = fmaf(w.z, dp0, f02); f03 = fmaf(w.w, dp0, f03);
                    f10 = fmaf(w.x, dp1, f10); f11 = fmaf(w.y, dp1, f11);
                    f12 = fmaf(w.z, dp1, f12); f13 = fmaf(w.w, dp1, f13);
                }
            }
#pragma unroll 2
            for (int q = 4; q < 8; q++) {          // recomputed channels
                float4 dv = dh4[q];
#pragma unroll
                for (int r = 0; r < 4; r++) {
                    const int k = 4 * q + r;
                    const float dhk = (r == 0) ? dv.x : (r == 1) ? dv.y : (r == 2) ? dv.z : dv.w;
                    const float4 w = w1c4[k];
                    float bias0 = biaskt[k][tt0];
                    float bias1 = biaskt[k][tt1];
                    float t0 = fmaf(rz0, w.w, fmaf(ry0, w.z, fmaf(rx0, w.y, w.x)));
                    float t1 = fmaf(rz1, w.w, fmaf(ry1, w.z, fmaf(rx1, w.y, w.x)));
                    float h0 = ftanh(fmaf(s0, t0, bias0));
                    float h1 = ftanh(fmaf(s1, t1, bias1));
                    float dp0 = dhk * fmaf(-h0, h0, 1.0f);
                    float dp1 = dhk * fmaf(-h1, h1, 1.0f);
                    f00 = fmaf(w.x, dp0, f00); f01 = fmaf(w.y, dp0, f01);
                    f02 = fmaf(w.z, dp0, f02); f03 = fmaf(w.w, dp0, f03);
                    f10 = fmaf(w.x, dp1, f10); f11 = fmaf(w.y, dp1, f11);
                    f12 = fmaf(w.z, dp1, f12); f13 = fmaf(w.w, dp1, f13);
                }
            }

            // ------------ epilogue per neighbor -----------------------------
            float cgx = 0.f, cgy = 0.f, cgz = 0.f;
#pragma unroll
            for (int nb = 0; nb < 2; nb++) {
                const bool valid = nb ? v1b : v0b;
                if (!valid) continue;
                const float rx = nb ? rx1 : rx0, ry = nb ? ry1 : ry0, rz = nb ? rz1 : rz0;
                const float s = nb ? s1 : s0, fcp = nb ? fcp1 : fcp0;
                const float ivd = nb ? ivd1 : ivd0, e = nb ? e1 : e0;
                const float fa = nb ? f10 : f00, fb = nb ? f11 : f01;
                const float fcq = nb ? f12 : f02, fd = nb ? f13 : f03;
                const int ni = nb ? ni1 : ni0;

                float ds = fa + rx * fb + ry * fcq + rz * fd;
                float dd = ds * fmaf(e, fcp, -s);  // e*(fcp - fc) = e*fcp - s
                float t2 = dd * ivd;
                float gx = fmaf(t2, rx, s * fb);
                float gy = fmaf(t2, ry, s * fcq);
                float gz = fmaf(t2, rz, s * fd);

                float pv0 = rx * gx, pv1 = rx * gy, pv2 = rx * gz;
                float pv3 = ry * gx, pv4 = ry * gy, pv5 = ry * gz;
                float pv6 = rz * gx, pv7 = rz * gy, pv8 = rz * gz;
                vir[0] += pv0; vir[1] += pv1; vir[2] += pv2;
                vir[3] += pv3; vir[4] += pv4; vir[5] += pv5;
                vir[6] += pv6; vir[7] += pv7; vir[8] += pv8;
                cgx += gx; cgy += gy; cgz += gz;

                if (ni < n) {
                    float* p = (float*)(g_scratch + ((long)bi * n + ni) * 3);
                    red_add_v4(p,     pv0, pv1, pv2, pv3);
                    red_add_v4(p + 4, pv4, pv5, pv6, pv7);
                    red_add_v4(p + 8, pv8, -gx, -gy, -gz);
                }
            }
            float cx = warp_sum(cgx), cy = warp_sum(cgy), cz = warp_sum(cgz);
            if (lane == 0) {
                float* p = (float*)(g_scratch + ((long)bi * n + ai) * 3);
                red_add_v4(p + 8, 0.0f, cx, cy, cz);
            }
        }
        if (cur_bi >= 0) flush_stats(vir, etot, cur_bi, st, lane);
    }

    // ================= device-wide barrier (ticket, monotonic) =============
    __syncthreads();
    if (tid == 0) {
        __threadfence();
        unsigned long long t = atomicAdd(&g_ctr, 1ULL);
        unsigned long long target = (t / (unsigned long long)G + 1ULL) * (unsigned long long)G;
        volatile unsigned long long* vc = (volatile unsigned long long*)&g_ctr;
        while (*vc < target) __nanosleep(128);
        __threadfence();
    }
    __syncthreads();

    // ================= pack phase (scratch -> out, then zero) ==============
    {
        const float4 z = make_float4(0.f, 0.f, 0.f, 0.f);
        const long stride = (long)G * THREADS;
        for (long i = (long)blockIdx.x * THREADS + tid; i < total; i += stride) {
            float4* r4 = &g_scratch[i * 3];
            float4 v0 = r4[0], v1 = r4[1], v2 = r4[2];
            r4[0] = z; r4[1] = z; r4[2] = z;
            float* outF  = out + b + total + i * 3;
            float* outAV = out + 10L * b + 4L * total + i * 9;
            outAV[0] = v0.x; outAV[1] = v0.y; outAV[2] = v0.z;
            outAV[3] = v0.w; outAV[4] = v1.x; outAV[5] = v1.y;
            outAV[6] = v1.z; outAV[7] = v1.w; outAV[8] = v2.x;
            outF[0] = v2.y; outF[1] = v2.z; outF[2] = v2.w;
        }
        if (blockIdx.x == 0) {
            for (int q = tid; q < b; q += THREADS) {
                out[q] = st[q]; st[q] = 0.0f;                          // Etot
            }
            for (int q = tid; q < 9 * b; q += THREADS) {
                out[b + 4L * total + q] = st[32 + q]; st[32 + q] = 0.0f; // virial
            }
        }
    }
}

// ---------------------------------------------------------------------------
extern "C" void kernel_launch(void* const* d_in, const int* in_sizes, int n_in,
                              void* d_out, int out_size) {
    const int*    element_map      = (const int*)d_in[0];
    const int*    neighbor_indices = (const int*)d_in[2];
    const int*    neighbor_types   = (const int*)d_in[3];
    const float4* neighbor_vectors = (const float4*)d_in[4];
    const float*  type_embed = (const float*)d_in[6];
    const float*  elem_bias  = (const float*)d_in[7];
    const float*  W1 = (const float*)d_in[8];
    const float*  b1 = (const float*)d_in[9];
    const float*  W2 = (const float*)d_in[10];
    const float*  b2 = (const float*)d_in[11];
    const float*  W3 = (const float*)d_in[12];
    const float*  b3 = (const float*)d_in[13];
    float* out = (float*)d_out;

    const int bn  = in_sizes[0];
    const int bnm = in_sizes[2];
    const int m   = bnm / bn;
    const int ntypes = in_sizes[7];
    int b = (int)(((long)out_size - 13L * bn) / 10L);
    if (b < 1) b = 1;
    const int n = bn / b;

    // persistent grid sized to exactly-resident occupancy (deadlock-free)
    int dev = 0;
    cudaGetDevice(&dev);
    int nsm = 0;
    cudaDeviceGetAttribute(&nsm, cudaDevAttrMultiProcessorCount, dev);
    if (nsm < 1) nsm = 148;
    int nb = 0;
    if (m == 64) {
        cudaOccupancyMaxActiveBlocksPerMultiprocessor(&nb, field_kernel<true>, THREADS, 0);
    } else {
        cudaOccupancyMaxActiveBlocksPerMultiprocessor(&nb, field_kernel<false>, THREADS, 0);
    }
    if (nb < 1) nb = 1;
    long grid = (long)nb * nsm;
    long maxBlocks = ((long)bn + NWARP - 1) / NWARP;
    if (grid > maxBlocks) grid = maxBlocks;
    if (grid < 1) grid = 1;

    if (m == 64) {
        field_kernel<true><<<(int)grid, THREADS>>>(element_map, neighbor_indices, neighbor_types,
                                                   neighbor_vectors, type_embed, elem_bias,
                                                   W1, b1, W2, b2, W3, b3, out, b, n, m, ntypes);
    } else {
        field_kernel<false><<<(int)grid, THREADS>>>(element_map, neighbor_indices, neighbor_types,
                                                    neighbor_vectors, type_embed, elem_bias,
                                                    W1, b1, W2, b2, W3, b3, out, b, n, m, ntypes);
    }
}